// round 5
// baseline (speedup 1.0000x reference)
#include <cuda_runtime.h>
#include <cuda_fp16.h>
#include <cstdint>

// ============================================================
// Problem sizes
// ============================================================
#define M_TOT   16384        // B*S
#define K_DIM   2048
#define N_TOT   2048
#define LEAF    13
#define RANK    4

// ============================================================
// GEMM tiling
// ============================================================
#define BM      128
#define BN      128
#define BK      32
#define STAGES  4
#define NUM_IT  (K_DIM / BK)            // 64
#define SSTRIDE 40                      // halves per smem row (80 B) — pad kills bank conflicts
#define A_HALVES     (BM * SSTRIDE)     // 5120
#define STAGE_HALVES (2 * A_HALVES)     // 10240 (A then B)
#define SMEM_BYTES   (STAGES * STAGE_HALVES * 2)   // 81920

// ============================================================
// Device scratch (allocation-free rule: __device__ globals)
// ============================================================
__device__ __half g_xh[(size_t)M_TOT * K_DIM];   // 64 MB
__device__ __half g_wh[(size_t)N_TOT * K_DIM];   // 8 MB

// ============================================================
// Helpers
// ============================================================
__device__ __forceinline__ uint32_t smem_u32(const void* p) {
    return (uint32_t)__cvta_generic_to_shared(p);
}

#define CP_ASYNC_16(dst_u32, src_ptr) \
    asm volatile("cp.async.cg.shared.global [%0], [%1], 16;" \
                 :: "r"(dst_u32), "l"(src_ptr))
#define CP_COMMIT() asm volatile("cp.async.commit_group;" ::: "memory")
#define CP_WAIT2()  asm volatile("cp.async.wait_group 2;" ::: "memory")

#define LDMATRIX_X4(r0, r1, r2, r3, addr) \
    asm volatile("ldmatrix.sync.aligned.m8n8.x4.shared.b16 {%0,%1,%2,%3}, [%4];" \
                 : "=r"(r0), "=r"(r1), "=r"(r2), "=r"(r3) : "r"(addr))

#define MMA_16816(c, a0, a1, a2, a3, b0, b1) \
    asm volatile("mma.sync.aligned.m16n8k16.row.col.f32.f16.f16.f32 " \
                 "{%0,%1,%2,%3}, {%4,%5,%6,%7}, {%8,%9}, {%0,%1,%2,%3};" \
                 : "+f"((c)[0]), "+f"((c)[1]), "+f"((c)[2]), "+f"((c)[3]) \
                 : "r"(a0), "r"(a1), "r"(a2), "r"(a3), "r"(b0), "r"(b1))

// ============================================================
// Prep 1: x (f32) -> fp16 (rne)
// ============================================================
__global__ void round_x_kernel(const float4* __restrict__ in, uint4* __restrict__ out, int n8) {
    int i = blockIdx.x * blockDim.x + threadIdx.x;
    int stride = gridDim.x * blockDim.x;
    for (; i < n8; i += stride) {
        float4 v0 = in[2 * i];
        float4 v1 = in[2 * i + 1];
        __half2 h0 = __floats2half2_rn(v0.x, v0.y);
        __half2 h1 = __floats2half2_rn(v0.z, v0.w);
        __half2 h2 = __floats2half2_rn(v1.x, v1.y);
        __half2 h3 = __floats2half2_rn(v1.z, v1.w);
        uint4 o;
        o.x = *(uint32_t*)&h0; o.y = *(uint32_t*)&h1;
        o.z = *(uint32_t*)&h2; o.w = *(uint32_t*)&h3;
        out[i] = o;
    }
}

// ============================================================
// Prep 2: w = fp16(weight + kron-delta)
// delta[o,i] = sum_r L0[r,o/169,i/169]*L1[r,(o/13)%13,(i/13)%13]*L2[r,o%13,i%13]
// ============================================================
__global__ void prep_w_kernel(const float* __restrict__ weight,
                              const float* __restrict__ leaf,
                              __half* __restrict__ wout) {
    __shared__ float L[3 * RANK * LEAF * LEAF];   // 2028 floats
    for (int i = threadIdx.x; i < 3 * RANK * LEAF * LEAF; i += blockDim.x)
        L[i] = leaf[i];
    __syncthreads();
    int o = blockIdx.x;
    int o0 = o / 169, o1 = (o / 13) % 13, o2 = o % 13;
    for (int i = threadIdx.x; i < K_DIM; i += blockDim.x) {
        int i0 = i / 169, i1 = (i / 13) % 13, i2 = i % 13;
        float d = 0.f;
#pragma unroll
        for (int r = 0; r < RANK; r++) {
            float a = L[((0 * RANK + r) * LEAF + o0) * LEAF + i0];
            float b = L[((1 * RANK + r) * LEAF + o1) * LEAF + i1];
            float c = L[((2 * RANK + r) * LEAF + o2) * LEAF + i2];
            d += a * b * c;
        }
        wout[(size_t)o * K_DIM + i] = __float2half_rn(weight[(size_t)o * K_DIM + i] + d);
    }
}

// ============================================================
// GEMM: out[m,n] = sum_k xh[m,k] * wh[n,k] + bias[n]
// 128x128x32 CTA tile, 8 warps (warp tile 64x32), 4-stage cp.async.
// ============================================================
__global__ void __launch_bounds__(256, 1)
gemm_kernel(const __half* __restrict__ xh,
            const __half* __restrict__ wh,
            const float* __restrict__ bias,
            float* __restrict__ out) {
    extern __shared__ __half smem[];

    const int tid  = threadIdx.x;
    const int wid  = tid >> 5;
    const int lane = tid & 31;

    // ---- tile swizzle: groups of 8 M-tiles sweep all 16 N-tiles (B stays in L2)
    const int NT = N_TOT / BN;               // 16
    const int per = 8 * NT;                  // 128
    const int g = blockIdx.x / per;
    const int r = blockIdx.x % per;
    const int tm = g * 8 + (r & 7);
    const int tn = r >> 3;
    const int m0 = tm * BM;
    const int n0 = tn * BN;

    // ---- global load coords (per thread: 2 A rows + 2 B rows, 16B each)
    const int ld_row = tid >> 2;             // 0..63
    const int ld_col = (tid & 3) * 8;        // 0,8,16,24
    const __half* ga0 = xh + (size_t)(m0 + ld_row) * K_DIM + ld_col;
    const __half* ga1 = ga0 + (size_t)64 * K_DIM;
    const __half* gb0 = wh + (size_t)(n0 + ld_row) * K_DIM + ld_col;
    const __half* gb1 = gb0 + (size_t)64 * K_DIM;
    const uint32_t sa0 = smem_u32(smem) + (ld_row * SSTRIDE + ld_col) * 2;
    const uint32_t sa1 = sa0 + 64 * SSTRIDE * 2;
    const uint32_t sb0 = sa0 + A_HALVES * 2;
    const uint32_t sb1 = sb0 + 64 * SSTRIDE * 2;

    // ---- warp/fragment coords
    const int wm = (wid & 1) * 64;           // warp M offset (2 M-warps)
    const int wn = (wid >> 1) * 32;          // warp N offset (4 N-warps)
    // A ldmatrix lane map (x4: quads = [r0-7@c0, r8-15@c0, r0-7@c8, r8-15@c8])
    const int a_r = (lane & 7) + ((lane >> 3) & 1) * 8;
    const int a_c = (lane >> 4) * 8;
    // B ldmatrix lane map (x4: quads = [n0-7@k0, n0-7@k8, n8-15@k0, n8-15@k8])
    const int b_n = (lane & 7) + ((lane & 16) ? 8 : 0);
    const int b_k = (lane & 8) ? 8 : 0;

    const uint32_t smem_base = smem_u32(smem);

    float acc[4][4][4];
#pragma unroll
    for (int i = 0; i < 4; i++)
#pragma unroll
        for (int j = 0; j < 4; j++)
#pragma unroll
            for (int v = 0; v < 4; v++) acc[i][j][v] = 0.f;

    // ---- prologue: prefetch stages 0..2
#pragma unroll
    for (int s = 0; s < STAGES - 1; s++) {
        const uint32_t so = s * STAGE_HALVES * 2;
        const size_t ko = (size_t)s * BK;
        CP_ASYNC_16(sa0 + so, ga0 + ko);
        CP_ASYNC_16(sa1 + so, ga1 + ko);
        CP_ASYNC_16(sb0 + so, gb0 + ko);
        CP_ASYNC_16(sb1 + so, gb1 + ko);
        CP_COMMIT();
    }

    for (int it = 0; it < NUM_IT; ++it) {
        CP_WAIT2();
        __syncthreads();

        const int slot = it & (STAGES - 1);
        const uint32_t abase = smem_base + slot * STAGE_HALVES * 2;
        const uint32_t bbase = abase + A_HALVES * 2;

        // ---- load all fragments for this BK=32 slab (2 k-steps)
        uint32_t af[2][4][4], bf[2][2][4];
#pragma unroll
        for (int ks = 0; ks < 2; ks++) {
#pragma unroll
            for (int i = 0; i < 4; i++) {
                uint32_t addr = abase + ((wm + i * 16 + a_r) * SSTRIDE + ks * 16 + a_c) * 2;
                LDMATRIX_X4(af[ks][i][0], af[ks][i][1], af[ks][i][2], af[ks][i][3], addr);
            }
#pragma unroll
            for (int j = 0; j < 2; j++) {
                uint32_t addr = bbase + ((wn + j * 16 + b_n) * SSTRIDE + ks * 16 + b_k) * 2;
                LDMATRIX_X4(bf[ks][j][0], bf[ks][j][1], bf[ks][j][2], bf[ks][j][3], addr);
            }
        }

        // ---- 32 MMAs
#pragma unroll
        for (int ks = 0; ks < 2; ks++)
#pragma unroll
            for (int i = 0; i < 4; i++)
#pragma unroll
                for (int j = 0; j < 4; j++) {
                    const uint32_t* bq = bf[ks][j >> 1];
                    MMA_16816(acc[i][j],
                              af[ks][i][0], af[ks][i][1], af[ks][i][2], af[ks][i][3],
                              bq[(j & 1) * 2], bq[(j & 1) * 2 + 1]);
                }

        // ---- prefetch stage it+3 into slot (it+3)%4 (empty commit in tail)
        const int nxt = it + STAGES - 1;
        if (nxt < NUM_IT) {
            const uint32_t so = (nxt & (STAGES - 1)) * STAGE_HALVES * 2;
            const size_t ko = (size_t)nxt * BK;
            CP_ASYNC_16(sa0 + so, ga0 + ko);
            CP_ASYNC_16(sa1 + so, ga1 + ko);
            CP_ASYNC_16(sb0 + so, gb0 + ko);
            CP_ASYNC_16(sb1 + so, gb1 + ko);
        }
        CP_COMMIT();
    }

    // ---- epilogue: bias add + direct stores (float2)
    const int gr = lane >> 2;            // 0..7
    const int gc = (lane & 3) * 2;
    float bv[4][2];
#pragma unroll
    for (int j = 0; j < 4; j++) {
        bv[j][0] = __ldg(&bias[n0 + wn + j * 8 + gc]);
        bv[j][1] = __ldg(&bias[n0 + wn + j * 8 + gc + 1]);
    }
#pragma unroll
    for (int i = 0; i < 4; i++) {
        const int row0 = m0 + wm + i * 16 + gr;
#pragma unroll
        for (int j = 0; j < 4; j++) {
            const int col = n0 + wn + j * 8 + gc;
            float2 v0 = make_float2(acc[i][j][0] + bv[j][0], acc[i][j][1] + bv[j][1]);
            float2 v1 = make_float2(acc[i][j][2] + bv[j][0], acc[i][j][3] + bv[j][1]);
            *reinterpret_cast<float2*>(out + (size_t)row0 * N_TOT + col) = v0;
            *reinterpret_cast<float2*>(out + (size_t)(row0 + 8) * N_TOT + col) = v1;
        }
    }
}

// ============================================================
// Host launch
// ============================================================
extern "C" void kernel_launch(void* const* d_in, const int* in_sizes, int n_in,
                              void* d_out, int out_size) {
    const float* x      = (const float*)d_in[0];
    const float* leaf   = (const float*)d_in[1];
    const float* weight = (const float*)d_in[2];
    const float* bias   = (const float*)d_in[3];
    float* out = (float*)d_out;

    void* xh_p = nullptr;
    void* wh_p = nullptr;
    cudaGetSymbolAddress(&xh_p, g_xh);
    cudaGetSymbolAddress(&wh_p, g_wh);

    round_x_kernel<<<4096, 256>>>((const float4*)x, (uint4*)xh_p,
                                  (int)((size_t)M_TOT * K_DIM / 8));
    prep_w_kernel<<<N_TOT, 256>>>(weight, leaf, (__half*)wh_p);

    // Unconditional (no static guard — forbidden by harness rules).
    // cudaFuncSetAttribute is not a stream op: safe under graph capture,
    // idempotent and deterministic.
    (void)cudaFuncSetAttribute(gemm_kernel,
                               cudaFuncAttributeMaxDynamicSharedMemorySize, SMEM_BYTES);

    const int grid = (M_TOT / BM) * (N_TOT / BN);   // 2048
    gemm_kernel<<<grid, 256, SMEM_BYTES>>>((const __half*)xh_p, (const __half*)wh_p,
                                           bias, out);
}